// round 10
// baseline (speedup 1.0000x reference)
#include <cuda_runtime.h>
#include <cuda_bf16.h>

#define NUM_BINS 32
#define NBINS2   (NUM_BINS * NUM_BINS)
#define EPS 1e-5f

// Zero-initialized device globals. Invariant: g_hist == 0 and g_done == 0 at
// kernel entry; the last CTA restores this before exit (deterministic replays).
__device__ unsigned int g_hist[NBINS2];
__device__ unsigned int g_done;

// Inputs are exact integers 0..255 stored as fp32. bin = rint(v/255*31).
// v*31/255 is never exactly k+0.5 and the nearest tie distance (1/510) far
// exceeds the fp32 error of v*fl(31/255) (~7e-6), so floor(v*c + 0.5) is
// bit-identical to the reference binning (verified rel_err == 0.0).
__device__ __forceinline__ int bin_of(float v) {
    const float c = 31.0f / 255.0f;
    return (int)__fmaf_rn(v, c, 0.5f);   // FFMA + F2I; truncation == floor (v>=0)
}

// Warp-aggregated increment: lanes with equal bins elect one leader that does
// a single fire-and-forget atomicAdd of the group count. Cuts ATOMS lane-ops
// by ~36% (E[distinct bins among 32 draws from 1024] ~= 20.4).
__device__ __forceinline__ void accum(unsigned int* sh, int bin, unsigned int lt_mask) {
    unsigned int peers = __match_any_sync(0xFFFFFFFFu, bin);
    if ((peers & lt_mask) == 0u)                  // leader = lowest peer lane
        atomicAdd(&sh[bin], (unsigned int)__popc(peers));
}

__device__ __forceinline__ void accum4(unsigned int* sh, float4 a, float4 b,
                                       unsigned int lt_mask) {
    accum(sh, bin_of(a.x) * NUM_BINS + bin_of(b.x), lt_mask);
    accum(sh, bin_of(a.y) * NUM_BINS + bin_of(b.y), lt_mask);
    accum(sh, bin_of(a.z) * NUM_BINS + bin_of(b.z), lt_mask);
    accum(sh, bin_of(a.w) * NUM_BINS + bin_of(b.w), lt_mask);
}

__global__ void __launch_bounds__(256) lmi_fused_kernel(
    const float4* __restrict__ I4,
    const float4* __restrict__ J4,
    int n4,
    float inv_total,
    float* __restrict__ out)
{
    __shared__ unsigned int sh[NBINS2];   // 4 KB CTA-shared histogram
    const int t = threadIdx.x;
    const unsigned int lt_mask = (1u << (t & 31)) - 1u;

    #pragma unroll
    for (int k = t; k < NBINS2; k += 256) sh[k] = 0u;
    __syncthreads();

    // ---- Phase 1: histogram (2x unrolled grid-stride, 4 LDG.128 in flight) ----
    const int stride = gridDim.x * blockDim.x;
    int i = blockIdx.x * blockDim.x + t;
    for (; i + stride < n4; i += 2 * stride) {
        float4 a0 = __ldcs(&I4[i]);
        float4 b0 = __ldcs(&J4[i]);
        float4 a1 = __ldcs(&I4[i + stride]);
        float4 b1 = __ldcs(&J4[i + stride]);
        accum4(sh, a0, b0, lt_mask);
        accum4(sh, a1, b1, lt_mask);
    }
    if (i < n4) {   // n4 is warp-aligned: condition is warp-uniform
        float4 a0 = __ldcs(&I4[i]);
        float4 b0 = __ldcs(&J4[i]);
        accum4(sh, a0, b0, lt_mask);
    }
    __syncthreads();

    // ---- Phase 2: flush CTA histogram to global (spread REDG, 4/thread) ----
    #pragma unroll
    for (int k = t; k < NBINS2; k += 256) {
        unsigned int v = sh[k];
        if (v) atomicAdd(&g_hist[k], v);
    }

    // ---- Phase 3: last CTA computes MI, writes out, resets state ----
    __shared__ bool is_last;
    __threadfence();   // order flush atomics before the counter
    if (t == 0) {
        unsigned int done = atomicAdd(&g_done, 1u);
        is_last = (done == gridDim.x - 1);
    }
    __syncthreads();
    if (!is_last) return;

    __shared__ float jp[NBINS2];
    __shared__ float rowp[NUM_BINS];
    __shared__ float colp[NUM_BINS];
    __shared__ float wsum[8];

    #pragma unroll
    for (int u = 0; u < 4; u++) {
        int k = t + u * 256;
        unsigned int v = __ldcg(&g_hist[k]);  // bypass L1: atomics landed in L2
        jp[k] = (float)v * inv_total;
        g_hist[k] = 0u;                       // restore invariant for next replay
    }
    if (t == 0) g_done = 0u;
    __syncthreads();

    if (t < NUM_BINS) {
        float s = 0.0f;
        #pragma unroll
        for (int c = 0; c < NUM_BINS; c++) s += jp[t * NUM_BINS + c];
        rowp[t] = s;
    } else if (t < 2 * NUM_BINS) {
        int c = t - NUM_BINS;
        float s = 0.0f;
        #pragma unroll
        for (int r = 0; r < NUM_BINS; r++) s += jp[r * NUM_BINS + c];
        colp[c] = s;
    }
    __syncthreads();

    float term = 0.0f;
    #pragma unroll
    for (int u = 0; u < 4; u++) {
        int b = t + u * 256;
        float p  = jp[b];
        float pi = rowp[b >> 5];
        float pj = colp[b & 31];
        term += p * (logf(p + EPS) - logf(pi + EPS) - logf(pj + EPS));
    }

    #pragma unroll
    for (int off = 16; off > 0; off >>= 1)
        term += __shfl_xor_sync(0xFFFFFFFFu, term, off);
    if ((t & 31) == 0) wsum[t >> 5] = term;
    __syncthreads();
    if (t < 8) {
        float s = wsum[t];
        #pragma unroll
        for (int off = 4; off > 0; off >>= 1)
            s += __shfl_xor_sync(0xFFu, s, off);
        if (t == 0) {
            out[0] = 1.0f / (1.0f + expf(s));   // sigmoid(-mi)
        }
    }
}

extern "C" void kernel_launch(void* const* d_in, const int* in_sizes, int n_in,
                              void* d_out, int out_size)
{
    const float* I = (const float*)d_in[0];
    const float* J = (const float*)d_in[1];
    float* out = (float*)d_out;
    const int n  = in_sizes[0];   // 33,554,432
    const int n4 = n / 4;

    const int threads = 256;
    const int blocks  = 148 * 8;  // 1184 CTAs, 8/SM (4 KB smem each)
    lmi_fused_kernel<<<blocks, threads>>>((const float4*)I, (const float4*)J,
                                          n4, 1.0f / (float)n, out);
}

// round 11
// speedup vs baseline: 1.1837x; 1.1837x over previous
#include <cuda_runtime.h>
#include <cuda_bf16.h>

#define NUM_BINS 32
#define NBINS2   (NUM_BINS * NUM_BINS)
#define NREP     32                       // global histogram replicas
#define EPS 1e-5f

// Zero-initialized device globals. Invariant: g_rep == 0 and g_done == 0 at
// kernel entry; the last CTA restores this before exit (deterministic replays).
__device__ unsigned int g_rep[NREP * NBINS2];   // 128 KB, replica-major
__device__ unsigned int g_done;

// Inputs are exact integers 0..255 stored as fp32. bin = rint(v/255*31).
// v*31/255 is never exactly k+0.5 and the nearest tie distance (1/510) far
// exceeds the fp32 error of v*fl(31/255) (~7e-6), so floor(v*c + 0.5) is
// bit-identical to the reference binning (verified rel_err == 0.0).
__device__ __forceinline__ int bin_of(float v) {
    const float c = 31.0f / 255.0f;
    return (int)__fmaf_rn(v, c, 0.5f);   // FFMA + F2I; truncation == floor (v>=0)
}

__global__ void __launch_bounds__(256) lmi_fused_kernel(
    const float4* __restrict__ I4,
    const float4* __restrict__ J4,
    int n4,
    float inv_total,
    float* __restrict__ out)
{
    __shared__ unsigned int sh[NBINS2];   // 4 KB CTA-shared histogram
    const int t = threadIdx.x;
    unsigned int* __restrict__ grep = &g_rep[(blockIdx.x & (NREP - 1)) << 10];

    #pragma unroll
    for (int k = t; k < NBINS2; k += 256) sh[k] = 0u;
    __syncthreads();

    // ---- Phase 1: histogram. Per 8 elements: 5 increments via smem ATOMS,
    // 3 via global REDG (fire-and-forget) — two independent atomic pipes. ----
    const int stride = gridDim.x * blockDim.x;
    int i = blockIdx.x * blockDim.x + t;
    for (; i + stride < n4; i += 2 * stride) {
        float4 a0 = __ldcs(&I4[i]);
        float4 b0 = __ldcs(&J4[i]);
        float4 a1 = __ldcs(&I4[i + stride]);
        float4 b1 = __ldcs(&J4[i + stride]);
        // 5 -> shared atomic unit
        atomicAdd(&sh[bin_of(a0.x) * NUM_BINS + bin_of(b0.x)], 1u);
        atomicAdd(&sh[bin_of(a0.y) * NUM_BINS + bin_of(b0.y)], 1u);
        atomicAdd(&sh[bin_of(a0.z) * NUM_BINS + bin_of(b0.z)], 1u);
        atomicAdd(&sh[bin_of(a0.w) * NUM_BINS + bin_of(b0.w)], 1u);
        atomicAdd(&sh[bin_of(a1.x) * NUM_BINS + bin_of(b1.x)], 1u);
        // 3 -> L2 atomic ALUs (REDG, no return value)
        atomicAdd(&grep[bin_of(a1.y) * NUM_BINS + bin_of(b1.y)], 1u);
        atomicAdd(&grep[bin_of(a1.z) * NUM_BINS + bin_of(b1.z)], 1u);
        atomicAdd(&grep[bin_of(a1.w) * NUM_BINS + bin_of(b1.w)], 1u);
    }
    if (i < n4) {
        float4 a0 = __ldcs(&I4[i]);
        float4 b0 = __ldcs(&J4[i]);
        atomicAdd(&sh[bin_of(a0.x) * NUM_BINS + bin_of(b0.x)], 1u);
        atomicAdd(&sh[bin_of(a0.y) * NUM_BINS + bin_of(b0.y)], 1u);
        atomicAdd(&grep[bin_of(a0.z) * NUM_BINS + bin_of(b0.z)], 1u);
        atomicAdd(&grep[bin_of(a0.w) * NUM_BINS + bin_of(b0.w)], 1u);
    }
    __syncthreads();

    // ---- Phase 2: flush CTA histogram into this CTA's replica ----
    #pragma unroll
    for (int k = t; k < NBINS2; k += 256) {
        unsigned int v = sh[k];
        if (v) atomicAdd(&grep[k], v);
    }

    // ---- Phase 3: last CTA reduces replicas, computes MI, resets state ----
    __shared__ bool is_last;
    __threadfence();   // order all atomics above before the counter
    if (t == 0) {
        unsigned int done = atomicAdd(&g_done, 1u);
        is_last = (done == gridDim.x - 1);
    }
    __syncthreads();
    if (!is_last) return;

    __shared__ float jp[NBINS2];
    __shared__ float rowp[NUM_BINS];
    __shared__ float colp[NUM_BINS];
    __shared__ float wsum[8];

    // Sum 32 replicas per bin (4 bins/thread, 128 L2 loads each, deep MLP),
    // then zero them to restore the replay invariant.
    #pragma unroll
    for (int u = 0; u < 4; u++) {
        int k = t + u * 256;
        unsigned int s = 0u;
        #pragma unroll
        for (int r = 0; r < NREP; r++)
            s += __ldcg(&g_rep[(r << 10) + k]);
        jp[k] = (float)s * inv_total;
        #pragma unroll
        for (int r = 0; r < NREP; r++)
            g_rep[(r << 10) + k] = 0u;
    }
    if (t == 0) g_done = 0u;
    __syncthreads();

    if (t < NUM_BINS) {
        float s = 0.0f;
        #pragma unroll
        for (int c = 0; c < NUM_BINS; c++) s += jp[t * NUM_BINS + c];
        rowp[t] = s;
    } else if (t < 2 * NUM_BINS) {
        int c = t - NUM_BINS;
        float s = 0.0f;
        #pragma unroll
        for (int r = 0; r < NUM_BINS; r++) s += jp[r * NUM_BINS + c];
        colp[c] = s;
    }
    __syncthreads();

    float term = 0.0f;
    #pragma unroll
    for (int u = 0; u < 4; u++) {
        int b = t + u * 256;
        float p  = jp[b];
        float pi = rowp[b >> 5];
        float pj = colp[b & 31];
        term += p * (logf(p + EPS) - logf(pi + EPS) - logf(pj + EPS));
    }

    #pragma unroll
    for (int off = 16; off > 0; off >>= 1)
        term += __shfl_xor_sync(0xFFFFFFFFu, term, off);
    if ((t & 31) == 0) wsum[t >> 5] = term;
    __syncthreads();
    if (t < 8) {
        float s = wsum[t];
        #pragma unroll
        for (int off = 4; off > 0; off >>= 1)
            s += __shfl_xor_sync(0xFFu, s, off);
        if (t == 0) {
            out[0] = 1.0f / (1.0f + expf(s));   // sigmoid(-mi)
        }
    }
}

extern "C" void kernel_launch(void* const* d_in, const int* in_sizes, int n_in,
                              void* d_out, int out_size)
{
    const float* I = (const float*)d_in[0];
    const float* J = (const float*)d_in[1];
    float* out = (float*)d_out;
    const int n  = in_sizes[0];   // 33,554,432
    const int n4 = n / 4;

    const int threads = 256;
    const int blocks  = 148 * 8;  // 1184 CTAs, 8/SM (4 KB smem each)
    lmi_fused_kernel<<<blocks, threads>>>((const float4*)I, (const float4*)J,
                                          n4, 1.0f / (float)n, out);
}

// round 12
// speedup vs baseline: 2.2273x; 1.8816x over previous
#include <cuda_runtime.h>
#include <cuda_bf16.h>

#define NUM_BINS 32
#define NBINS2   (NUM_BINS * NUM_BINS)
#define NCTAS    1184                  // hist grid (148 SMs x 8)
#define NRED     148                   // reduce grid; NCTAS = NRED * 8
#define EPS 1e-5f

// Zero-initialized device globals. Invariant: all zero at graph-replay entry;
// the reduce kernel restores this before exiting (deterministic replays).
__device__ unsigned int g_rep[NCTAS * NBINS2];  // 4.85 MB: CTA-PRIVATE replicas
__device__ unsigned int g_hist[NBINS2];
__device__ unsigned int g_done;

// Inputs are exact integers 0..255 stored as fp32. bin = rint(v/255*31).
// v*31/255 is never exactly k+0.5 and the nearest tie distance (1/510) far
// exceeds the fp32 error of v*fl(31/255) (~7e-6), so floor(v*c + 0.5) is
// bit-identical to the reference binning (verified rel_err == 0.0).
__device__ __forceinline__ int bin_of(float v) {
    const float c = 31.0f / 255.0f;
    return (int)__fmaf_rn(v, c, 0.5f);   // FFMA + F2I; truncation == floor (v>=0)
}

__global__ void __launch_bounds__(256) lmi_hist_kernel(
    const float4* __restrict__ I4,
    const float4* __restrict__ J4,
    int n4)
{
    __shared__ unsigned int sh[NBINS2];   // 4 KB CTA-shared histogram
    const int t = threadIdx.x;
    // CTA-PRIVATE replica: no cross-CTA address sharing -> uncontended L2 atomics
    unsigned int* __restrict__ grep = &g_rep[blockIdx.x << 10];

    #pragma unroll
    for (int k = t; k < NBINS2; k += 256) sh[k] = 0u;
    __syncthreads();

    // ---- Phase 1: per 8 elements, 5 -> smem ATOMS, 3 -> private-replica REDG.
    // Two independent atomic pipes; ATOMS load drops below the DRAM floor. ----
    const int stride = gridDim.x * blockDim.x;
    int i = blockIdx.x * blockDim.x + t;
    for (; i + stride < n4; i += 2 * stride) {
        float4 a0 = __ldcs(&I4[i]);
        float4 b0 = __ldcs(&J4[i]);
        float4 a1 = __ldcs(&I4[i + stride]);
        float4 b1 = __ldcs(&J4[i + stride]);
        atomicAdd(&sh[bin_of(a0.x) * NUM_BINS + bin_of(b0.x)], 1u);
        atomicAdd(&sh[bin_of(a0.y) * NUM_BINS + bin_of(b0.y)], 1u);
        atomicAdd(&sh[bin_of(a0.z) * NUM_BINS + bin_of(b0.z)], 1u);
        atomicAdd(&sh[bin_of(a0.w) * NUM_BINS + bin_of(b0.w)], 1u);
        atomicAdd(&sh[bin_of(a1.x) * NUM_BINS + bin_of(b1.x)], 1u);
        atomicAdd(&grep[bin_of(a1.y) * NUM_BINS + bin_of(b1.y)], 1u);
        atomicAdd(&grep[bin_of(a1.z) * NUM_BINS + bin_of(b1.z)], 1u);
        atomicAdd(&grep[bin_of(a1.w) * NUM_BINS + bin_of(b1.w)], 1u);
    }
    if (i < n4) {
        float4 a0 = __ldcs(&I4[i]);
        float4 b0 = __ldcs(&J4[i]);
        atomicAdd(&sh[bin_of(a0.x) * NUM_BINS + bin_of(b0.x)], 1u);
        atomicAdd(&sh[bin_of(a0.y) * NUM_BINS + bin_of(b0.y)], 1u);
        atomicAdd(&grep[bin_of(a0.z) * NUM_BINS + bin_of(b0.z)], 1u);
        atomicAdd(&grep[bin_of(a0.w) * NUM_BINS + bin_of(b0.w)], 1u);
    }
    __syncthreads();

    // ---- Phase 2: flush CTA histogram to g_hist (same pattern as R8) ----
    #pragma unroll
    for (int k = t; k < NBINS2; k += 256) {
        unsigned int v = sh[k];
        if (v) atomicAdd(&g_hist[k], v);
    }
}

__global__ void __launch_bounds__(256) lmi_reduce_kernel(float* __restrict__ out,
                                                         float inv_total)
{
    const int t = threadIdx.x;
    const int c = blockIdx.x;

    // ---- Sum this CTA's 8 replicas into g_hist; zero them for next replay.
    // Layout: g_rep viewed as uint4[NCTAS*256]; thread t owns bins 4t..4t+3. ----
    uint4* rep4 = (uint4*)g_rep;
    unsigned int s0 = 0u, s1 = 0u, s2 = 0u, s3 = 0u;
    #pragma unroll
    for (int r = 0; r < 8; r++) {
        int idx = ((c * 8 + r) << 8) + t;
        uint4 v = __ldcg(&rep4[idx]);
        s0 += v.x; s1 += v.y; s2 += v.z; s3 += v.w;
        rep4[idx] = make_uint4(0u, 0u, 0u, 0u);
    }
    int b = t << 2;
    if (s0) atomicAdd(&g_hist[b + 0], s0);
    if (s1) atomicAdd(&g_hist[b + 1], s1);
    if (s2) atomicAdd(&g_hist[b + 2], s2);
    if (s3) atomicAdd(&g_hist[b + 3], s3);

    // ---- Last CTA: MI epilogue + state reset ----
    __shared__ bool is_last;
    __threadfence();
    if (t == 0) {
        unsigned int done = atomicAdd(&g_done, 1u);
        is_last = (done == gridDim.x - 1);
    }
    __syncthreads();
    if (!is_last) return;

    __shared__ float jp[NBINS2];
    __shared__ float rowp[NUM_BINS];
    __shared__ float colp[NUM_BINS];
    __shared__ float wsum[8];

    #pragma unroll
    for (int u = 0; u < 4; u++) {
        int k = t + u * 256;
        unsigned int v = __ldcg(&g_hist[k]);  // bypass L1: atomics landed in L2
        jp[k] = (float)v * inv_total;
        g_hist[k] = 0u;                       // restore invariant
    }
    if (t == 0) g_done = 0u;
    __syncthreads();

    if (t < NUM_BINS) {
        float s = 0.0f;
        #pragma unroll
        for (int cc = 0; cc < NUM_BINS; cc++) s += jp[t * NUM_BINS + cc];
        rowp[t] = s;
    } else if (t < 2 * NUM_BINS) {
        int cc = t - NUM_BINS;
        float s = 0.0f;
        #pragma unroll
        for (int r = 0; r < NUM_BINS; r++) s += jp[r * NUM_BINS + cc];
        colp[cc] = s;
    }
    __syncthreads();

    float term = 0.0f;
    #pragma unroll
    for (int u = 0; u < 4; u++) {
        int k = t + u * 256;
        float p  = jp[k];
        float pi = rowp[k >> 5];
        float pj = colp[k & 31];
        term += p * (logf(p + EPS) - logf(pi + EPS) - logf(pj + EPS));
    }

    #pragma unroll
    for (int off = 16; off > 0; off >>= 1)
        term += __shfl_xor_sync(0xFFFFFFFFu, term, off);
    if ((t & 31) == 0) wsum[t >> 5] = term;
    __syncthreads();
    if (t < 8) {
        float s = wsum[t];
        #pragma unroll
        for (int off = 4; off > 0; off >>= 1)
            s += __shfl_xor_sync(0xFFu, s, off);
        if (t == 0) {
            out[0] = 1.0f / (1.0f + expf(s));   // sigmoid(-mi)
        }
    }
}

extern "C" void kernel_launch(void* const* d_in, const int* in_sizes, int n_in,
                              void* d_out, int out_size)
{
    const float* I = (const float*)d_in[0];
    const float* J = (const float*)d_in[1];
    float* out = (float*)d_out;
    const int n  = in_sizes[0];   // 33,554,432
    const int n4 = n / 4;

    lmi_hist_kernel<<<NCTAS, 256>>>((const float4*)I, (const float4*)J, n4);
    lmi_reduce_kernel<<<NRED, 256>>>(out, 1.0f / (float)n);
}

// round 17
// speedup vs baseline: 4.3510x; 1.9535x over previous
#include <cuda_runtime.h>
#include <cuda_bf16.h>

#define NUM_BINS 32
#define NBINS2   (NUM_BINS * NUM_BINS)
#define EPS 1e-5f

// Zero-initialized device globals. Invariant: g_hist == 0 and g_done == 0 at
// kernel entry; the last CTA restores this before exit (deterministic replays).
__device__ unsigned int g_hist[NBINS2];
__device__ unsigned int g_done;

// Inputs are exact integers 0..255 stored as fp32. bin = rint(v/255*31).
// v*31/255 is never exactly k+0.5 and the nearest tie distance (1/510) far
// exceeds the fp32 error of v*fl(31/255) (~7e-6), so floor(v*c + 0.5) is
// bit-identical to the reference binning (verified rel_err == 0.0).
__device__ __forceinline__ int bin_of(float v) {
    const float c = 31.0f / 255.0f;
    return (int)__fmaf_rn(v, c, 0.5f);   // FFMA + F2I; truncation == floor (v>=0)
}

__device__ __forceinline__ void accum4(unsigned int* sh, float4 a, float4 b) {
    // smem ATOMS: fire-and-forget, the proven fastest increment path
    atomicAdd(&sh[bin_of(a.x) * NUM_BINS + bin_of(b.x)], 1u);
    atomicAdd(&sh[bin_of(a.y) * NUM_BINS + bin_of(b.y)], 1u);
    atomicAdd(&sh[bin_of(a.z) * NUM_BINS + bin_of(b.z)], 1u);
    atomicAdd(&sh[bin_of(a.w) * NUM_BINS + bin_of(b.w)], 1u);
}

__global__ void __launch_bounds__(256) lmi_fused_kernel(
    const float4* __restrict__ I4,
    const float4* __restrict__ J4,
    int n4,
    float inv_total,
    float* __restrict__ out)
{
    __shared__ unsigned int sh[NBINS2];   // 4 KB CTA-shared histogram
    const int t = threadIdx.x;

    #pragma unroll
    for (int k = t; k < NBINS2; k += 256) sh[k] = 0u;
    __syncthreads();

    // ---- Phase 1: histogram. 4x unrolled grid-stride: 8 LDG.128 in flight
    // keeps DRAM saturated while the smem ATOMS unit (the binding resource,
    // ~2 lanes/cyc/SM) drains at its floor. ----
    const int stride = gridDim.x * blockDim.x;
    int i = blockIdx.x * blockDim.x + t;

    for (; i + 3 * stride < n4; i += 4 * stride) {
        float4 a0 = __ldcs(&I4[i]);
        float4 b0 = __ldcs(&J4[i]);
        float4 a1 = __ldcs(&I4[i + stride]);
        float4 b1 = __ldcs(&J4[i + stride]);
        float4 a2 = __ldcs(&I4[i + 2 * stride]);
        float4 b2 = __ldcs(&J4[i + 2 * stride]);
        float4 a3 = __ldcs(&I4[i + 3 * stride]);
        float4 b3 = __ldcs(&J4[i + 3 * stride]);
        accum4(sh, a0, b0);
        accum4(sh, a1, b1);
        accum4(sh, a2, b2);
        accum4(sh, a3, b3);
    }
    for (; i < n4; i += stride) {
        float4 a0 = __ldcs(&I4[i]);
        float4 b0 = __ldcs(&J4[i]);
        accum4(sh, a0, b0);
    }
    __syncthreads();

    // ---- Phase 2: flush CTA histogram to global (4 REDG/thread) ----
    #pragma unroll
    for (int k = t; k < NBINS2; k += 256) {
        unsigned int v = sh[k];
        if (v) atomicAdd(&g_hist[k], v);
    }

    // ---- Phase 3: last CTA computes MI, writes out, resets state ----
    __shared__ bool is_last;
    __threadfence();   // order flush atomics before the counter
    if (t == 0) {
        unsigned int done = atomicAdd(&g_done, 1u);
        is_last = (done == gridDim.x - 1);
    }
    __syncthreads();
    if (!is_last) return;

    __shared__ float jp[NBINS2];
    __shared__ float rowp[NUM_BINS];
    __shared__ float colp[NUM_BINS];
    __shared__ float wsum[8];

    #pragma unroll
    for (int u = 0; u < 4; u++) {
        int k = t + u * 256;
        unsigned int v = __ldcg(&g_hist[k]);  // bypass L1: atomics landed in L2
        jp[k] = (float)v * inv_total;
        g_hist[k] = 0u;                       // restore invariant for next replay
    }
    if (t == 0) g_done = 0u;
    __syncthreads();

    if (t < NUM_BINS) {
        float s = 0.0f;
        #pragma unroll
        for (int c = 0; c < NUM_BINS; c++) s += jp[t * NUM_BINS + c];
        rowp[t] = s;
    } else if (t < 2 * NUM_BINS) {
        int c = t - NUM_BINS;
        float s = 0.0f;
        #pragma unroll
        for (int r = 0; r < NUM_BINS; r++) s += jp[r * NUM_BINS + c];
        colp[c] = s;
    }
    __syncthreads();

    float term = 0.0f;
    #pragma unroll
    for (int u = 0; u < 4; u++) {
        int b = t + u * 256;
        float p  = jp[b];
        float pi = rowp[b >> 5];
        float pj = colp[b & 31];
        term += p * (logf(p + EPS) - logf(pi + EPS) - logf(pj + EPS));
    }

    #pragma unroll
    for (int off = 16; off > 0; off >>= 1)
        term += __shfl_xor_sync(0xFFFFFFFFu, term, off);
    if ((t & 31) == 0) wsum[t >> 5] = term;
    __syncthreads();
    if (t < 8) {
        float s = wsum[t];
        #pragma unroll
        for (int off = 4; off > 0; off >>= 1)
            s += __shfl_xor_sync(0xFFu, s, off);
        if (t == 0) {
            out[0] = 1.0f / (1.0f + expf(s));   // sigmoid(-mi)
        }
    }
}

extern "C" void kernel_launch(void* const* d_in, const int* in_sizes, int n_in,
                              void* d_out, int out_size)
{
    const float* I = (const float*)d_in[0];
    const float* J = (const float*)d_in[1];
    float* out = (float*)d_out;
    const int n  = in_sizes[0];   // 33,554,432
    const int n4 = n / 4;

    const int threads = 256;
    const int blocks  = 148 * 8;  // 1184 CTAs, 8/SM (4 KB smem each)
    lmi_fused_kernel<<<blocks, threads>>>((const float4*)I, (const float4*)J,
                                          n4, 1.0f / (float)n, out);
}